// round 7
// baseline (speedup 1.0000x reference)
#include <cuda_runtime.h>
#include <cuda_bf16.h>
#include <math.h>
#include <stdint.h>

#define TSTEPS  20
#define NLAYERS 4
#define DM      512
#define DS      128
#define ROWS    2048      // BATCH(4) * SEQ(512)
#define VOCAB   32000

// ---------------- scratch (device globals; no allocations allowed) ----------
__device__ uint32_t      g_bits[2][TSTEPS][ROWS][16];
__device__ float         g_AT[NLAYERS][DS * DS];      // AT[j*DS+i] = A[i][j]
__device__ float         g_BT[NLAYERS][DM * DS];      // BT[d*DS+i] = B[i][d]
__device__ float         g_CT[NLAYERS][DS * DM];      // CT[i*DM+d] = C[d][i]
__device__ __nv_bfloat16 g_cntb[ROWS * DM];           // exact integer spike counts
__device__ __nv_bfloat16 g_wph[(size_t)VOCAB * DM];   // bf16 hi of Wp
__device__ __nv_bfloat16 g_wpl[(size_t)VOCAB * DM];   // bf16 lo of Wp

// ---------------- weight transposes ----------------------------------------
__global__ void prep_kernel(const float* __restrict__ A,
                            const float* __restrict__ Bm,
                            const float* __restrict__ Cm) {
    int stride = gridDim.x * blockDim.x;
    int gid = blockIdx.x * blockDim.x + threadIdx.x;
    for (int idx = gid; idx < NLAYERS * DS * DS; idx += stride) {
        int l = idx / (DS * DS); int rm = idx % (DS * DS);
        int i = rm / DS, j = rm % DS;
        g_AT[l][j * DS + i] = A[idx];
    }
    for (int idx = gid; idx < NLAYERS * DS * DM; idx += stride) {
        int l = idx / (DS * DM); int rm = idx % (DS * DM);
        int i = rm / DM, d = rm % DM;
        g_BT[l][d * DS + i] = Bm[idx];
    }
    for (int idx = gid; idx < NLAYERS * DM * DS; idx += stride) {
        int l = idx / (DM * DS); int rm = idx % (DM * DS);
        int d = rm / DS, i = rm % DS;
        g_CT[l][i * DM + d] = Cm[idx];
    }
}

// ---------------- Wp two-term bf16 split ------------------------------------
__global__ void split_wp_kernel(const float* __restrict__ Wp) {
    long long i = (long long)blockIdx.x * blockDim.x + threadIdx.x;
    if (i >= (long long)VOCAB * DM) return;
    float w = Wp[i];
    __nv_bfloat16 h = __float2bfloat16(w);
    g_wph[i] = h;
    g_wpl[i] = __float2bfloat16(w - __bfloat162float(h));
}

__global__ void zero_bits_kernel() {
    int gid = blockIdx.x * blockDim.x + threadIdx.x;
    uint32_t* p = &g_bits[0][0][0][0];
    int n = TSTEPS * ROWS * 16;
    for (int i = gid; i < n; i += gridDim.x * blockDim.x) p[i] = 0u;
}

// ---------------- temporal encoding (exact fp32 logistic, as validated) -----
__global__ void encode_kernel(const int* __restrict__ ids,
                              const float* __restrict__ emb) {
    int gid = blockIdx.x * blockDim.x + threadIdx.x;
    if (gid >= ROWS * DM) return;
    int r = gid >> 9, d = gid & (DM - 1);
    float x = emb[(long long)ids[r] * DM + d];
    float sgf = 1.0f / (1.0f + expf(-x));
    int t = (int)floorf(sgf * 19.0f);
    if (t < 0) t = 0;
    if (t > 19) t = 19;
    atomicOr(&g_bits[0][t][r][d >> 5], 1u << (d & 31));
}

// ---------------- one LIF-SSM layer (validated bit-exact, R5 unchanged) -----
__global__ __launch_bounds__(128) void ssm_kernel(int layer, int inb, int outb,
                                                  const float* __restrict__ Dfull) {
    int r   = blockIdx.x;
    int tid = threadIdx.x;
    int lane = tid & 31, wp = tid >> 5;
    const float* __restrict__ AT = g_AT[layer];
    const float* __restrict__ BT = g_BT[layer];
    const float* __restrict__ CT = g_CT[layer];
    const float* __restrict__ Dv = Dfull + layer * DM;

    __shared__ uint32_t sh_x[16];
    __shared__ uint32_t sh_h[4];
    __shared__ int sh_xidx[512];
    __shared__ int sh_hidx[128];
    __shared__ int sh_nx, sh_nh;

    float v1 = 0.f;
    float v2[4] = {0.f, 0.f, 0.f, 0.f};
    if (tid == 0) { sh_nh = 0; sh_nx = 0; }

    for (int t = 0; t < TSTEPS; t++) {
        __syncthreads();
        if (tid < 16) sh_x[tid] = g_bits[inb][t][r][tid];
        __syncthreads();

        if (tid < 16) {
            uint32_t w = sh_x[tid];
            int c = __popc(w);
            int incl = c;
            #pragma unroll
            for (int off = 1; off < 16; off <<= 1) {
                int y = __shfl_up_sync(0xffffu, incl, off);
                if (tid >= off) incl += y;
            }
            int pos = incl - c;
            while (w) {
                int b = __ffs(w) - 1; w &= w - 1;
                sh_xidx[pos++] = ((tid << 5) + b) * DS;
            }
            if (tid == 15) sh_nx = incl;
        }
        __syncthreads();

        int nh = sh_nh, nx = sh_nx;
        float sa = 0.f;
        #pragma unroll 4
        for (int i = 0; i < nh; i++) sa += AT[sh_hidx[i] * DS + tid];
        float sb = 0.f;
        #pragma unroll 4
        for (int i = 0; i < nx; i++) sb += BT[sh_xidx[i] + tid];
        float u = sa + sb;

        v1 = v1 + (u - v1) * 0.5f;
        int s1 = (v1 - 1.0f) >= 0.f;
        uint32_t hb = __ballot_sync(0xffffffffu, s1);
        if (s1) v1 = 0.f;
        __syncthreads();
        if (lane == 0) sh_h[wp] = hb;
        __syncthreads();

        if (tid < 4) {
            uint32_t w = sh_h[tid];
            int c = __popc(w);
            int incl = c;
            #pragma unroll
            for (int off = 1; off < 4; off <<= 1) {
                int y = __shfl_up_sync(0xfu, incl, off);
                if (tid >= off) incl += y;
            }
            int pos = incl - c;
            while (w) {
                int b = __ffs(w) - 1; w &= w - 1;
                sh_hidx[pos++] = (tid << 5) + b;
            }
            if (tid == 3) sh_nh = incl;
        }
        __syncthreads();

        int nh2 = sh_nh;
        float sc0 = 0.f, sc1 = 0.f, sc2 = 0.f, sc3 = 0.f;
        #pragma unroll 2
        for (int i = 0; i < nh2; i++) {
            const float* crow = CT + sh_hidx[i] * DM + tid;
            sc0 += crow[0];
            sc1 += crow[128];
            sc2 += crow[256];
            sc3 += crow[384];
        }
        float sc[4] = {sc0, sc1, sc2, sc3};
        #pragma unroll
        for (int k = 0; k < 4; k++) {
            float u2 = sc[k];
            if ((sh_x[4 * k + wp] >> lane) & 1u) u2 = u2 + Dv[tid + 128 * k];
            v2[k] = v2[k] + (u2 - v2[k]) * 0.5f;
            int s2 = (v2[k] - 1.0f) >= 0.f;
            uint32_t ob = __ballot_sync(0xffffffffu, s2);
            if (s2) v2[k] = 0.f;
            if (lane == 0) g_bits[outb][t][r][4 * k + wp] = ob;
        }
    }
}

// ---------------- spike counts over T (exact small ints, bf16) --------------
__global__ void count_kernel() {
    int gid = blockIdx.x * blockDim.x + threadIdx.x;
    if (gid >= ROWS * DM) return;
    int r = gid >> 9, d = gid & (DM - 1);
    int w = d >> 5, b = d & 31;
    int c = 0;
    #pragma unroll
    for (int t = 0; t < TSTEPS; t++) c += (g_bits[0][t][r][w] >> b) & 1u;
    g_cntb[gid] = __float2bfloat16((float)c);   // integers <= 20: exact in bf16
}

// ============ logits GEMM: split-bf16 mma.sync with cp.async pipeline ========
// Block tile 128x128, warps 2x4 (warp tile 64x32), K chunked x32, 4-stage
// cp.async pipeline (8B copies; 80B row pitch stays conflict-free for frag LDS).
#define SPAD   40                        // bf16 per smem row (80 B pitch)
#define KC     32                        // K per chunk
#define NCH    (DM / KC)                 // 16 chunks
#define ST     4                         // pipeline stages
#define MAT_B  (128 * SPAD * 2)          // 10240 B per matrix tile
#define STAGE_B (3 * MAT_B)              // A + Bh + Bl
#define GSMEM_BYTES (ST * STAGE_B)       // 122880

__device__ __forceinline__ void mma16816(float* d, const uint32_t* a, const uint32_t* b) {
    asm volatile(
        "mma.sync.aligned.m16n8k16.row.col.f32.bf16.bf16.f32 "
        "{%0,%1,%2,%3}, {%4,%5,%6,%7}, {%8,%9}, {%0,%1,%2,%3};"
        : "+f"(d[0]), "+f"(d[1]), "+f"(d[2]), "+f"(d[3])
        : "r"(a[0]), "r"(a[1]), "r"(a[2]), "r"(a[3]), "r"(b[0]), "r"(b[1]));
}
__device__ __forceinline__ void cpasync8(uint32_t dst, const void* src) {
    asm volatile("cp.async.ca.shared.global [%0], [%1], 8;" :: "r"(dst), "l"(src));
}
__device__ __forceinline__ uint32_t smem_u32(const void* p) {
    uint32_t a;
    asm("{ .reg .u64 t; cvta.to.shared.u64 t, %1; cvt.u32.u64 %0, t; }"
        : "=r"(a) : "l"(p));
    return a;
}

__global__ __launch_bounds__(256) void gemm_bf16_kernel(const float* __restrict__ bp,
                                                        float* __restrict__ out) {
    extern __shared__ char smem[];
    uint32_t sbase = smem_u32(smem);

    int bm = blockIdx.x, bn = blockIdx.y;   // bm fastest -> Wp tile reused in L2
    int tid = threadIdx.x;
    int w   = tid >> 5;
    int wm  = w >> 2, wn = w & 3;           // 2 x 4 warps
    int lane = tid & 31;
    int g = lane >> 2, tig = lane & 3;

    const __nv_bfloat16* asrc = g_cntb + (size_t)(bm * 128) * DM;
    const __nv_bfloat16* hsrc = g_wph  + (size_t)(bn * 128) * DM;
    const __nv_bfloat16* lsrc = g_wpl  + (size_t)(bn * 128) * DM;

    // copy mapping: 1024 8B-copies per matrix per stage; 4 per thread per matrix
    int crow = tid >> 1;                    // rows 0..127 (2 threads/row)
    // each thread handles segs {t&1, (t&1)+2, (t&1)+4, (t&1)+6}
    int cseg0 = tid & 1;

    auto issue_stage = [&](int s, int c) {
        uint32_t dbase = sbase + s * STAGE_B;
        const __nv_bfloat16* srcs[3] = {asrc, hsrc, lsrc};
        #pragma unroll
        for (int m = 0; m < 3; m++) {
            const __nv_bfloat16* gsrc = srcs[m] + (size_t)crow * DM + c * KC;
            uint32_t drow = dbase + m * MAT_B + crow * (SPAD * 2);
            #pragma unroll
            for (int j = 0; j < 4; j++) {
                int seg = cseg0 + 2 * j;
                cpasync8(drow + seg * 8, gsrc + seg * 4);
            }
        }
    };

    // prologue: fill ST-1 stages
    #pragma unroll
    for (int s = 0; s < ST - 1; s++) {
        issue_stage(s, s);
        asm volatile("cp.async.commit_group;" ::: "memory");
    }

    float acc[4][4][4];
    #pragma unroll
    for (int i = 0; i < 4; i++)
        #pragma unroll
        for (int j = 0; j < 4; j++)
            #pragma unroll
            for (int q = 0; q < 4; q++) acc[i][j][q] = 0.f;

    #pragma unroll 1
    for (int c = 0; c < NCH; c++) {
        asm volatile("cp.async.wait_group 2;" ::: "memory");
        __syncthreads();

        // issue chunk c+ST-1 into stage (c+ST-1)%ST (its consumers sync'd above)
        if (c + ST - 1 < NCH) issue_stage((c + ST - 1) % ST, c + ST - 1);
        asm volatile("cp.async.commit_group;" ::: "memory");

        const __nv_bfloat16* s_a  = (const __nv_bfloat16*)(smem + (c % ST) * STAGE_B);
        const __nv_bfloat16* s_bh = s_a + 128 * SPAD;
        const __nv_bfloat16* s_bl = s_bh + 128 * SPAD;

        #pragma unroll
        for (int ks = 0; ks < KC / 16; ks++) {
            uint32_t afr[4][4];
            #pragma unroll
            for (int mf = 0; mf < 4; mf++) {
                int m0 = wm * 64 + mf * 16;
                const __nv_bfloat16* base = s_a + (m0 + g) * SPAD + ks * 16 + 2 * tig;
                afr[mf][0] = *(const uint32_t*)(base);
                afr[mf][1] = *(const uint32_t*)(base + 8 * SPAD);
                afr[mf][2] = *(const uint32_t*)(base + 8);
                afr[mf][3] = *(const uint32_t*)(base + 8 * SPAD + 8);
            }
            #pragma unroll
            for (int nf = 0; nf < 4; nf++) {
                int n0 = wn * 32 + nf * 8;
                const __nv_bfloat16* hb = s_bh + (n0 + g) * SPAD + ks * 16 + 2 * tig;
                const __nv_bfloat16* lb = s_bl + (n0 + g) * SPAD + ks * 16 + 2 * tig;
                uint32_t bh[2], bl[2];
                bh[0] = *(const uint32_t*)(hb);
                bh[1] = *(const uint32_t*)(hb + 8);
                bl[0] = *(const uint32_t*)(lb);
                bl[1] = *(const uint32_t*)(lb + 8);
                #pragma unroll
                for (int mf = 0; mf < 4; mf++) {
                    mma16816(acc[mf][nf], afr[mf], bh);
                    mma16816(acc[mf][nf], afr[mf], bl);
                }
            }
        }
        __syncthreads();
    }

    // epilogue: logits = acc * (1/20) + bias
    #pragma unroll
    for (int nf = 0; nf < 4; nf++) {
        int col = bn * 128 + wn * 32 + nf * 8 + 2 * tig;
        float2 bias = *(const float2*)(bp + col);
        #pragma unroll
        for (int mf = 0; mf < 4; mf++) {
            int row0 = bm * 128 + wm * 64 + mf * 16 + g;
            float2 o0, o1;
            o0.x = acc[mf][nf][0] * 0.05f + bias.x;
            o0.y = acc[mf][nf][1] * 0.05f + bias.y;
            o1.x = acc[mf][nf][2] * 0.05f + bias.x;
            o1.y = acc[mf][nf][3] * 0.05f + bias.y;
            *(float2*)(out + (size_t)row0 * VOCAB + col)       = o0;
            *(float2*)(out + (size_t)(row0 + 8) * VOCAB + col) = o1;
        }
    }
}

// ---------------- launch -----------------------------------------------------
extern "C" void kernel_launch(void* const* d_in, const int* in_sizes, int n_in,
                              void* d_out, int out_size) {
    const int*   ids  = (const int*)d_in[0];
    const float* emb  = (const float*)d_in[1];
    const float* A    = (const float*)d_in[2];
    const float* Bm   = (const float*)d_in[3];
    const float* Cm   = (const float*)d_in[4];
    const float* Dm_  = (const float*)d_in[5];
    const float* Wp   = (const float*)d_in[6];
    const float* bp   = (const float*)d_in[7];
    float*       out  = (float*)d_out;

    prep_kernel<<<256, 256>>>(A, Bm, Cm);
    split_wp_kernel<<<(VOCAB * DM + 255) / 256, 256>>>(Wp);
    zero_bits_kernel<<<256, 256>>>();
    encode_kernel<<<(ROWS * DM + 255) / 256, 256>>>(ids, emb);

    ssm_kernel<<<ROWS, 128>>>(0, 0, 1, Dm_);
    ssm_kernel<<<ROWS, 128>>>(1, 1, 0, Dm_);
    ssm_kernel<<<ROWS, 128>>>(2, 0, 1, Dm_);
    ssm_kernel<<<ROWS, 128>>>(3, 1, 0, Dm_);

    count_kernel<<<(ROWS * DM + 255) / 256, 256>>>();

    cudaFuncSetAttribute(gemm_bf16_kernel,
                         cudaFuncAttributeMaxDynamicSharedMemorySize,
                         GSMEM_BYTES);
    gemm_bf16_kernel<<<dim3(ROWS / 128, VOCAB / 128), 256, GSMEM_BYTES>>>(bp, out);
}

// round 8
// speedup vs baseline: 1.0718x; 1.0718x over previous
#include <cuda_runtime.h>
#include <cuda_bf16.h>
#include <math.h>
#include <stdint.h>

#define TSTEPS  20
#define NLAYERS 4
#define DM      512
#define DS      128
#define ROWS    2048      // BATCH(4) * SEQ(512)
#define VOCAB   32000

// ---------------- scratch (device globals; no allocations allowed) ----------
__device__ uint32_t      g_bits[2][TSTEPS][ROWS][16];
__device__ float         g_AT[NLAYERS][DS * DS];      // AT[j*DS+i] = A[i][j]
__device__ float         g_BT[NLAYERS][DM * DS];      // BT[d*DS+i] = B[i][d]
__device__ float         g_CT[NLAYERS][DS * DM];      // CT[i*DM+d] = C[d][i]
__device__ __nv_bfloat16 g_cntb[ROWS * DM];           // exact integer spike counts
__device__ __nv_bfloat16 g_wph[(size_t)VOCAB * DM];   // bf16 hi of Wp
__device__ __nv_bfloat16 g_wpl[(size_t)VOCAB * DM];   // bf16 lo of Wp

// ---------------- weight transposes ----------------------------------------
__global__ void prep_kernel(const float* __restrict__ A,
                            const float* __restrict__ Bm,
                            const float* __restrict__ Cm) {
    int stride = gridDim.x * blockDim.x;
    int gid = blockIdx.x * blockDim.x + threadIdx.x;
    for (int idx = gid; idx < NLAYERS * DS * DS; idx += stride) {
        int l = idx / (DS * DS); int rm = idx % (DS * DS);
        int i = rm / DS, j = rm % DS;
        g_AT[l][j * DS + i] = A[idx];
    }
    for (int idx = gid; idx < NLAYERS * DS * DM; idx += stride) {
        int l = idx / (DS * DM); int rm = idx % (DS * DM);
        int i = rm / DM, d = rm % DM;
        g_BT[l][d * DS + i] = Bm[idx];
    }
    for (int idx = gid; idx < NLAYERS * DM * DS; idx += stride) {
        int l = idx / (DM * DS); int rm = idx % (DM * DS);
        int d = rm / DS, i = rm % DS;
        g_CT[l][i * DM + d] = Cm[idx];
    }
}

// ---------------- Wp two-term bf16 split ------------------------------------
__global__ void split_wp_kernel(const float* __restrict__ Wp) {
    long long i = (long long)blockIdx.x * blockDim.x + threadIdx.x;
    if (i >= (long long)VOCAB * DM) return;
    float w = Wp[i];
    __nv_bfloat16 h = __float2bfloat16(w);
    g_wph[i] = h;
    g_wpl[i] = __float2bfloat16(w - __bfloat162float(h));
}

__global__ void zero_bits_kernel() {
    int gid = blockIdx.x * blockDim.x + threadIdx.x;
    uint32_t* p = &g_bits[0][0][0][0];
    int n = TSTEPS * ROWS * 16;
    for (int i = gid; i < n; i += gridDim.x * blockDim.x) p[i] = 0u;
}

// ---------------- temporal encoding (exact fp32 logistic, as validated) -----
__global__ void encode_kernel(const int* __restrict__ ids,
                              const float* __restrict__ emb) {
    int gid = blockIdx.x * blockDim.x + threadIdx.x;
    if (gid >= ROWS * DM) return;
    int r = gid >> 9, d = gid & (DM - 1);
    float x = emb[(long long)ids[r] * DM + d];
    float sgf = 1.0f / (1.0f + expf(-x));
    int t = (int)floorf(sgf * 19.0f);
    if (t < 0) t = 0;
    if (t > 19) t = 19;
    atomicOr(&g_bits[0][t][r][d >> 5], 1u << (d & 31));
}

// ---------------- one LIF-SSM layer (validated bit-exact, R5 unchanged) -----
__global__ __launch_bounds__(128) void ssm_kernel(int layer, int inb, int outb,
                                                  const float* __restrict__ Dfull) {
    int r   = blockIdx.x;
    int tid = threadIdx.x;
    int lane = tid & 31, wp = tid >> 5;
    const float* __restrict__ AT = g_AT[layer];
    const float* __restrict__ BT = g_BT[layer];
    const float* __restrict__ CT = g_CT[layer];
    const float* __restrict__ Dv = Dfull + layer * DM;

    __shared__ uint32_t sh_x[16];
    __shared__ uint32_t sh_h[4];
    __shared__ int sh_xidx[512];
    __shared__ int sh_hidx[128];
    __shared__ int sh_nx, sh_nh;

    float v1 = 0.f;
    float v2[4] = {0.f, 0.f, 0.f, 0.f};
    if (tid == 0) { sh_nh = 0; sh_nx = 0; }

    for (int t = 0; t < TSTEPS; t++) {
        __syncthreads();
        if (tid < 16) sh_x[tid] = g_bits[inb][t][r][tid];
        __syncthreads();

        if (tid < 16) {
            uint32_t w = sh_x[tid];
            int c = __popc(w);
            int incl = c;
            #pragma unroll
            for (int off = 1; off < 16; off <<= 1) {
                int y = __shfl_up_sync(0xffffu, incl, off);
                if (tid >= off) incl += y;
            }
            int pos = incl - c;
            while (w) {
                int b = __ffs(w) - 1; w &= w - 1;
                sh_xidx[pos++] = ((tid << 5) + b) * DS;
            }
            if (tid == 15) sh_nx = incl;
        }
        __syncthreads();

        int nh = sh_nh, nx = sh_nx;
        float sa = 0.f;
        #pragma unroll 4
        for (int i = 0; i < nh; i++) sa += AT[sh_hidx[i] * DS + tid];
        float sb = 0.f;
        #pragma unroll 4
        for (int i = 0; i < nx; i++) sb += BT[sh_xidx[i] + tid];
        float u = sa + sb;

        v1 = v1 + (u - v1) * 0.5f;
        int s1 = (v1 - 1.0f) >= 0.f;
        uint32_t hb = __ballot_sync(0xffffffffu, s1);
        if (s1) v1 = 0.f;
        __syncthreads();
        if (lane == 0) sh_h[wp] = hb;
        __syncthreads();

        if (tid < 4) {
            uint32_t w = sh_h[tid];
            int c = __popc(w);
            int incl = c;
            #pragma unroll
            for (int off = 1; off < 4; off <<= 1) {
                int y = __shfl_up_sync(0xfu, incl, off);
                if (tid >= off) incl += y;
            }
            int pos = incl - c;
            while (w) {
                int b = __ffs(w) - 1; w &= w - 1;
                sh_hidx[pos++] = (tid << 5) + b;
            }
            if (tid == 3) sh_nh = incl;
        }
        __syncthreads();

        int nh2 = sh_nh;
        float sc0 = 0.f, sc1 = 0.f, sc2 = 0.f, sc3 = 0.f;
        #pragma unroll 2
        for (int i = 0; i < nh2; i++) {
            const float* crow = CT + sh_hidx[i] * DM + tid;
            sc0 += crow[0];
            sc1 += crow[128];
            sc2 += crow[256];
            sc3 += crow[384];
        }
        float sc[4] = {sc0, sc1, sc2, sc3};
        #pragma unroll
        for (int k = 0; k < 4; k++) {
            float u2 = sc[k];
            if ((sh_x[4 * k + wp] >> lane) & 1u) u2 = u2 + Dv[tid + 128 * k];
            v2[k] = v2[k] + (u2 - v2[k]) * 0.5f;
            int s2 = (v2[k] - 1.0f) >= 0.f;
            uint32_t ob = __ballot_sync(0xffffffffu, s2);
            if (s2) v2[k] = 0.f;
            if (lane == 0) g_bits[outb][t][r][4 * k + wp] = ob;
        }
    }
}

// ---------------- spike counts over T (exact small ints, bf16) --------------
__global__ void count_kernel() {
    int gid = blockIdx.x * blockDim.x + threadIdx.x;
    if (gid >= ROWS * DM) return;
    int r = gid >> 9, d = gid & (DM - 1);
    int w = d >> 5, b = d & 31;
    int c = 0;
    #pragma unroll
    for (int t = 0; t < TSTEPS; t++) c += (g_bits[0][t][r][w] >> b) & 1u;
    g_cntb[gid] = __float2bfloat16((float)c);   // integers <= 20: exact in bf16
}

// ============ logits GEMM: split-bf16 mma.sync, 3-stage cp.async =============
// Block tile 128x128, warps 2x4 (warp tile 64x32), K chunked x32, 3 stages,
// 92KB smem -> 2 CTAs/SM (16 warps). wait_group 1 steady / 0 on last chunk.
#define SPAD   40                        // bf16 per smem row (80 B pitch)
#define KC     32                        // K per chunk
#define NCH    (DM / KC)                 // 16 chunks
#define ST     3                         // pipeline stages
#define MAT_B  (128 * SPAD * 2)          // 10240 B per matrix tile
#define STAGE_B (3 * MAT_B)              // A + Bh + Bl
#define GSMEM_BYTES (ST * STAGE_B)       // 92160

__device__ __forceinline__ void mma16816(float* d, const uint32_t* a, const uint32_t* b) {
    asm volatile(
        "mma.sync.aligned.m16n8k16.row.col.f32.bf16.bf16.f32 "
        "{%0,%1,%2,%3}, {%4,%5,%6,%7}, {%8,%9}, {%0,%1,%2,%3};"
        : "+f"(d[0]), "+f"(d[1]), "+f"(d[2]), "+f"(d[3])
        : "r"(a[0]), "r"(a[1]), "r"(a[2]), "r"(a[3]), "r"(b[0]), "r"(b[1]));
}
__device__ __forceinline__ void cpasync16(uint32_t dst, const void* src) {
    asm volatile("cp.async.ca.shared.global [%0], [%1], 16;" :: "r"(dst), "l"(src));
}
__device__ __forceinline__ uint32_t smem_u32(const void* p) {
    uint32_t a;
    asm("{ .reg .u64 t; cvta.to.shared.u64 t, %1; cvt.u32.u64 %0, t; }"
        : "=r"(a) : "l"(p));
    return a;
}

__global__ __launch_bounds__(256, 2) void gemm_bf16_kernel(const float* __restrict__ bp,
                                                           float* __restrict__ out) {
    extern __shared__ char smem[];
    uint32_t sbase = smem_u32(smem);

    int bm = blockIdx.x, bn = blockIdx.y;   // bm fastest -> Wp tile reused in L2
    int tid = threadIdx.x;
    int w   = tid >> 5;
    int wm  = w >> 2, wn = w & 3;           // 2 x 4 warps
    int lane = tid & 31;
    int g = lane >> 2, tig = lane & 3;

    const __nv_bfloat16* asrc = g_cntb + (size_t)(bm * 128) * DM;
    const __nv_bfloat16* hsrc = g_wph  + (size_t)(bn * 128) * DM;
    const __nv_bfloat16* lsrc = g_wpl  + (size_t)(bn * 128) * DM;

    // copy mapping: per stage each matrix tile is 128 rows x 64B; 2 threads/row,
    // each thread does 2x16B per matrix (6 cp.async per stage).
    int crow  = tid >> 1;
    int chalf = (tid & 1) * 32;             // byte offset of 32B half within row

    auto issue_stage = [&](int s, int c) {
        uint32_t dbase = sbase + s * STAGE_B + crow * (SPAD * 2) + chalf;
        size_t goff = (size_t)crow * DM + c * KC + (chalf >> 1);
        cpasync16(dbase,                 asrc + goff);
        cpasync16(dbase + 16,            asrc + goff + 8);
        cpasync16(dbase + MAT_B,         hsrc + goff);
        cpasync16(dbase + MAT_B + 16,    hsrc + goff + 8);
        cpasync16(dbase + 2 * MAT_B,     lsrc + goff);
        cpasync16(dbase + 2 * MAT_B + 16, lsrc + goff + 8);
    };

    // prologue: fill ST-1 stages
    #pragma unroll
    for (int s = 0; s < ST - 1; s++) {
        issue_stage(s, s);
        asm volatile("cp.async.commit_group;" ::: "memory");
    }

    float acc[4][4][4];
    #pragma unroll
    for (int i = 0; i < 4; i++)
        #pragma unroll
        for (int j = 0; j < 4; j++)
            #pragma unroll
            for (int q = 0; q < 4; q++) acc[i][j][q] = 0.f;

    #pragma unroll 1
    for (int c = 0; c < NCH; c++) {
        // at loop top, chunks c and (maybe) c+1 are in flight
        if (c < NCH - 1) asm volatile("cp.async.wait_group 1;" ::: "memory");
        else             asm volatile("cp.async.wait_group 0;" ::: "memory");
        __syncthreads();

        if (c + 2 < NCH) {                  // buffer (c+2)%ST freed by the sync
            issue_stage((c + 2) % ST, c + 2);
            asm volatile("cp.async.commit_group;" ::: "memory");
        }

        const __nv_bfloat16* s_a  = (const __nv_bfloat16*)(smem + (c % ST) * STAGE_B);
        const __nv_bfloat16* s_bh = s_a + 128 * SPAD;
        const __nv_bfloat16* s_bl = s_bh + 128 * SPAD;

        #pragma unroll
        for (int ks = 0; ks < KC / 16; ks++) {
            uint32_t afr[4][4];
            #pragma unroll
            for (int mf = 0; mf < 4; mf++) {
                int m0 = wm * 64 + mf * 16;
                const __nv_bfloat16* base = s_a + (m0 + g) * SPAD + ks * 16 + 2 * tig;
                afr[mf][0] = *(const uint32_t*)(base);
                afr[mf][1] = *(const uint32_t*)(base + 8 * SPAD);
                afr[mf][2] = *(const uint32_t*)(base + 8);
                afr[mf][3] = *(const uint32_t*)(base + 8 * SPAD + 8);
            }
            #pragma unroll
            for (int nf = 0; nf < 4; nf++) {
                int n0 = wn * 32 + nf * 8;
                const __nv_bfloat16* hb = s_bh + (n0 + g) * SPAD + ks * 16 + 2 * tig;
                const __nv_bfloat16* lb = s_bl + (n0 + g) * SPAD + ks * 16 + 2 * tig;
                uint32_t bh[2], bl[2];
                bh[0] = *(const uint32_t*)(hb);
                bh[1] = *(const uint32_t*)(hb + 8);
                bl[0] = *(const uint32_t*)(lb);
                bl[1] = *(const uint32_t*)(lb + 8);
                #pragma unroll
                for (int mf = 0; mf < 4; mf++) {
                    mma16816(acc[mf][nf], afr[mf], bh);
                    mma16816(acc[mf][nf], afr[mf], bl);
                }
            }
        }
        __syncthreads();
    }

    // epilogue: logits = acc * (1/20) + bias
    #pragma unroll
    for (int nf = 0; nf < 4; nf++) {
        int col = bn * 128 + wn * 32 + nf * 8 + 2 * tig;
        float2 bias = *(const float2*)(bp + col);
        #pragma unroll
        for (int mf = 0; mf < 4; mf++) {
            int row0 = bm * 128 + wm * 64 + mf * 16 + g;
            float2 o0, o1;
            o0.x = acc[mf][nf][0] * 0.05f + bias.x;
            o0.y = acc[mf][nf][1] * 0.05f + bias.y;
            o1.x = acc[mf][nf][2] * 0.05f + bias.x;
            o1.y = acc[mf][nf][3] * 0.05f + bias.y;
            *(float2*)(out + (size_t)row0 * VOCAB + col)       = o0;
            *(float2*)(out + (size_t)(row0 + 8) * VOCAB + col) = o1;
        }
    }
}

// ---------------- launch -----------------------------------------------------
extern "C" void kernel_launch(void* const* d_in, const int* in_sizes, int n_in,
                              void* d_out, int out_size) {
    const int*   ids  = (const int*)d_in[0];
    const float* emb  = (const float*)d_in[1];
    const float* A    = (const float*)d_in[2];
    const float* Bm   = (const float*)d_in[3];
    const float* Cm   = (const float*)d_in[4];
    const float* Dm_  = (const float*)d_in[5];
    const float* Wp   = (const float*)d_in[6];
    const float* bp   = (const float*)d_in[7];
    float*       out  = (float*)d_out;

    prep_kernel<<<256, 256>>>(A, Bm, Cm);
    split_wp_kernel<<<(VOCAB * DM + 255) / 256, 256>>>(Wp);
    zero_bits_kernel<<<256, 256>>>();
    encode_kernel<<<(ROWS * DM + 255) / 256, 256>>>(ids, emb);

    ssm_kernel<<<ROWS, 128>>>(0, 0, 1, Dm_);
    ssm_kernel<<<ROWS, 128>>>(1, 1, 0, Dm_);
    ssm_kernel<<<ROWS, 128>>>(2, 0, 1, Dm_);
    ssm_kernel<<<ROWS, 128>>>(3, 1, 0, Dm_);

    count_kernel<<<(ROWS * DM + 255) / 256, 256>>>();

    cudaFuncSetAttribute(gemm_bf16_kernel,
                         cudaFuncAttributeMaxDynamicSharedMemorySize,
                         GSMEM_BYTES);
    gemm_bf16_kernel<<<dim3(ROWS / 128, VOCAB / 128), 256, GSMEM_BYTES>>>(bp, out);
}

// round 9
// speedup vs baseline: 1.0947x; 1.0213x over previous
#include <cuda_runtime.h>
#include <cuda_bf16.h>
#include <math.h>
#include <stdint.h>

#define TSTEPS  20
#define NLAYERS 4
#define DM      512
#define DS      128
#define ROWS    2048      // BATCH(4) * SEQ(512)
#define VOCAB   32000

// ---------------- scratch (device globals; no allocations allowed) ----------
__device__ uint32_t      g_bits[2][TSTEPS][ROWS][16];
__device__ float         g_AT[NLAYERS][DS * DS];      // AT[j*DS+i] = A[i][j]
__device__ float         g_BT[NLAYERS][DM * DS];      // BT[d*DS+i] = B[i][d]
__device__ float         g_CT[NLAYERS][DS * DM];      // CT[i*DM+d] = C[d][i]
__device__ __nv_bfloat16 g_cntb[ROWS * DM];           // exact integer spike counts
__device__ __nv_bfloat16 g_wph[(size_t)VOCAB * DM];   // bf16 hi of Wp
__device__ __nv_bfloat16 g_wpl[(size_t)VOCAB * DM];   // bf16 lo of Wp

// ---------------- weight transposes ----------------------------------------
__global__ void prep_kernel(const float* __restrict__ A,
                            const float* __restrict__ Bm,
                            const float* __restrict__ Cm) {
    int stride = gridDim.x * blockDim.x;
    int gid = blockIdx.x * blockDim.x + threadIdx.x;
    for (int idx = gid; idx < NLAYERS * DS * DS; idx += stride) {
        int l = idx / (DS * DS); int rm = idx % (DS * DS);
        int i = rm / DS, j = rm % DS;
        g_AT[l][j * DS + i] = A[idx];
    }
    for (int idx = gid; idx < NLAYERS * DS * DM; idx += stride) {
        int l = idx / (DS * DM); int rm = idx % (DS * DM);
        int i = rm / DM, d = rm % DM;
        g_BT[l][d * DS + i] = Bm[idx];
    }
    for (int idx = gid; idx < NLAYERS * DM * DS; idx += stride) {
        int l = idx / (DM * DS); int rm = idx % (DM * DS);
        int d = rm / DS, i = rm % DS;
        g_CT[l][i * DM + d] = Cm[idx];
    }
}

// ---------------- Wp two-term bf16 split ------------------------------------
__global__ void split_wp_kernel(const float* __restrict__ Wp) {
    long long i = (long long)blockIdx.x * blockDim.x + threadIdx.x;
    if (i >= (long long)VOCAB * DM) return;
    float w = Wp[i];
    __nv_bfloat16 h = __float2bfloat16(w);
    g_wph[i] = h;
    g_wpl[i] = __float2bfloat16(w - __bfloat162float(h));
}

__global__ void zero_bits_kernel() {
    int gid = blockIdx.x * blockDim.x + threadIdx.x;
    uint32_t* p = &g_bits[0][0][0][0];
    int n = TSTEPS * ROWS * 16;
    for (int i = gid; i < n; i += gridDim.x * blockDim.x) p[i] = 0u;
}

// ---------------- temporal encoding (exact fp32 logistic, as validated) -----
__global__ void encode_kernel(const int* __restrict__ ids,
                              const float* __restrict__ emb) {
    int gid = blockIdx.x * blockDim.x + threadIdx.x;
    if (gid >= ROWS * DM) return;
    int r = gid >> 9, d = gid & (DM - 1);
    float x = emb[(long long)ids[r] * DM + d];
    float sgf = 1.0f / (1.0f + expf(-x));
    int t = (int)floorf(sgf * 19.0f);
    if (t < 0) t = 0;
    if (t > 19) t = 19;
    atomicOr(&g_bits[0][t][r][d >> 5], 1u << (d & 31));
}

// ---------------- one LIF-SSM layer (validated bit-exact, R5 unchanged) -----
__global__ __launch_bounds__(128) void ssm_kernel(int layer, int inb, int outb,
                                                  const float* __restrict__ Dfull) {
    int r   = blockIdx.x;
    int tid = threadIdx.x;
    int lane = tid & 31, wp = tid >> 5;
    const float* __restrict__ AT = g_AT[layer];
    const float* __restrict__ BT = g_BT[layer];
    const float* __restrict__ CT = g_CT[layer];
    const float* __restrict__ Dv = Dfull + layer * DM;

    __shared__ uint32_t sh_x[16];
    __shared__ uint32_t sh_h[4];
    __shared__ int sh_xidx[512];
    __shared__ int sh_hidx[128];
    __shared__ int sh_nx, sh_nh;

    float v1 = 0.f;
    float v2[4] = {0.f, 0.f, 0.f, 0.f};
    if (tid == 0) { sh_nh = 0; sh_nx = 0; }

    for (int t = 0; t < TSTEPS; t++) {
        __syncthreads();
        if (tid < 16) sh_x[tid] = g_bits[inb][t][r][tid];
        __syncthreads();

        if (tid < 16) {
            uint32_t w = sh_x[tid];
            int c = __popc(w);
            int incl = c;
            #pragma unroll
            for (int off = 1; off < 16; off <<= 1) {
                int y = __shfl_up_sync(0xffffu, incl, off);
                if (tid >= off) incl += y;
            }
            int pos = incl - c;
            while (w) {
                int b = __ffs(w) - 1; w &= w - 1;
                sh_xidx[pos++] = ((tid << 5) + b) * DS;
            }
            if (tid == 15) sh_nx = incl;
        }
        __syncthreads();

        int nh = sh_nh, nx = sh_nx;
        float sa = 0.f;
        #pragma unroll 4
        for (int i = 0; i < nh; i++) sa += AT[sh_hidx[i] * DS + tid];
        float sb = 0.f;
        #pragma unroll 4
        for (int i = 0; i < nx; i++) sb += BT[sh_xidx[i] + tid];
        float u = sa + sb;

        v1 = v1 + (u - v1) * 0.5f;
        int s1 = (v1 - 1.0f) >= 0.f;
        uint32_t hb = __ballot_sync(0xffffffffu, s1);
        if (s1) v1 = 0.f;
        __syncthreads();
        if (lane == 0) sh_h[wp] = hb;
        __syncthreads();

        if (tid < 4) {
            uint32_t w = sh_h[tid];
            int c = __popc(w);
            int incl = c;
            #pragma unroll
            for (int off = 1; off < 4; off <<= 1) {
                int y = __shfl_up_sync(0xfu, incl, off);
                if (tid >= off) incl += y;
            }
            int pos = incl - c;
            while (w) {
                int b = __ffs(w) - 1; w &= w - 1;
                sh_hidx[pos++] = (tid << 5) + b;
            }
            if (tid == 3) sh_nh = incl;
        }
        __syncthreads();

        int nh2 = sh_nh;
        float sc0 = 0.f, sc1 = 0.f, sc2 = 0.f, sc3 = 0.f;
        #pragma unroll 2
        for (int i = 0; i < nh2; i++) {
            const float* crow = CT + sh_hidx[i] * DM + tid;
            sc0 += crow[0];
            sc1 += crow[128];
            sc2 += crow[256];
            sc3 += crow[384];
        }
        float sc[4] = {sc0, sc1, sc2, sc3};
        #pragma unroll
        for (int k = 0; k < 4; k++) {
            float u2 = sc[k];
            if ((sh_x[4 * k + wp] >> lane) & 1u) u2 = u2 + Dv[tid + 128 * k];
            v2[k] = v2[k] + (u2 - v2[k]) * 0.5f;
            int s2 = (v2[k] - 1.0f) >= 0.f;
            uint32_t ob = __ballot_sync(0xffffffffu, s2);
            if (s2) v2[k] = 0.f;
            if (lane == 0) g_bits[outb][t][r][4 * k + wp] = ob;
        }
    }
}

// ---------------- spike counts over T (exact small ints, bf16) --------------
__global__ void count_kernel() {
    int gid = blockIdx.x * blockDim.x + threadIdx.x;
    if (gid >= ROWS * DM) return;
    int r = gid >> 9, d = gid & (DM - 1);
    int w = d >> 5, b = d & 31;
    int c = 0;
    #pragma unroll
    for (int t = 0; t < TSTEPS; t++) c += (g_bits[0][t][r][w] >> b) & 1u;
    g_cntb[gid] = __float2bfloat16((float)c);   // integers <= 20: exact in bf16
}

// ============ logits GEMM: split-bf16 mma.sync + ldmatrix, 3-stage cp.async ==
// Block tile 128x128, warps 2x4 (warp tile 64x32), K chunked x32, 3 stages,
// 92KB smem -> 2 CTAs/SM. Fragments via ldmatrix (80B pitch is conflict-free:
// rows of an 8x8 tile land on banks {0,20,8,28,16,4,24,12}).
#define SPAD   40                        // bf16 per smem row (80 B pitch)
#define KC     32                        // K per chunk
#define NCH    (DM / KC)                 // 16 chunks
#define ST     3                         // pipeline stages
#define MAT_B  (128 * SPAD * 2)          // 10240 B per matrix tile
#define STAGE_B (3 * MAT_B)              // A + Bh + Bl
#define GSMEM_BYTES (ST * STAGE_B)       // 92160

__device__ __forceinline__ void mma16816(float* d, const uint32_t* a, const uint32_t* b) {
    asm volatile(
        "mma.sync.aligned.m16n8k16.row.col.f32.bf16.bf16.f32 "
        "{%0,%1,%2,%3}, {%4,%5,%6,%7}, {%8,%9}, {%0,%1,%2,%3};"
        : "+f"(d[0]), "+f"(d[1]), "+f"(d[2]), "+f"(d[3])
        : "r"(a[0]), "r"(a[1]), "r"(a[2]), "r"(a[3]), "r"(b[0]), "r"(b[1]));
}
__device__ __forceinline__ void ldmx4(uint32_t* r, uint32_t a) {
    asm volatile("ldmatrix.sync.aligned.m8n8.x4.shared.b16 {%0,%1,%2,%3}, [%4];"
        : "=r"(r[0]), "=r"(r[1]), "=r"(r[2]), "=r"(r[3]) : "r"(a));
}
__device__ __forceinline__ void ldmx2(uint32_t* r, uint32_t a) {
    asm volatile("ldmatrix.sync.aligned.m8n8.x2.shared.b16 {%0,%1}, [%2];"
        : "=r"(r[0]), "=r"(r[1]) : "r"(a));
}
__device__ __forceinline__ void cpasync16(uint32_t dst, const void* src) {
    asm volatile("cp.async.ca.shared.global [%0], [%1], 16;" :: "r"(dst), "l"(src));
}
__device__ __forceinline__ uint32_t smem_u32(const void* p) {
    uint32_t a;
    asm("{ .reg .u64 t; cvta.to.shared.u64 t, %1; cvt.u32.u64 %0, t; }"
        : "=r"(a) : "l"(p));
    return a;
}

__global__ __launch_bounds__(256, 2) void gemm_bf16_kernel(const float* __restrict__ bp,
                                                           float* __restrict__ out) {
    extern __shared__ char smem[];
    uint32_t sbase = smem_u32(smem);

    int bm = blockIdx.x, bn = blockIdx.y;   // bm fastest -> Wp tile reused in L2
    int tid = threadIdx.x;
    int w   = tid >> 5;
    int wm  = w >> 2, wn = w & 3;           // 2 x 4 warps
    int lane = tid & 31;
    int g = lane >> 2, tig = lane & 3;

    const __nv_bfloat16* asrc = g_cntb + (size_t)(bm * 128) * DM;
    const __nv_bfloat16* hsrc = g_wph  + (size_t)(bn * 128) * DM;
    const __nv_bfloat16* lsrc = g_wpl  + (size_t)(bn * 128) * DM;

    // ldmatrix per-lane address offsets (bytes, within a stage's matrix tile)
    int a_q = lane >> 3, a_r = lane & 7;
    uint32_t a_off = (uint32_t)(((wm * 64 + (a_q & 1) * 8 + a_r) * SPAD +
                                 (a_q >> 1) * 8) * 2);
    int b_r = lane & 7, b_q = (lane >> 3) & 1;   // lanes 16-31 mirror 0-15 (x2)
    uint32_t b_off = (uint32_t)(((wn * 32 + b_r) * SPAD + b_q * 8) * 2);

    // copy mapping: per stage each matrix tile is 128 rows x 64B; 2 threads/row,
    // each thread does 2x16B per matrix (6 cp.async per stage).
    int crow  = tid >> 1;
    int chalf = (tid & 1) * 32;             // byte offset of 32B half within row

    auto issue_stage = [&](int s, int c) {
        uint32_t dbase = sbase + s * STAGE_B + crow * (SPAD * 2) + chalf;
        size_t goff = (size_t)crow * DM + c * KC + (chalf >> 1);
        cpasync16(dbase,                  asrc + goff);
        cpasync16(dbase + 16,             asrc + goff + 8);
        cpasync16(dbase + MAT_B,          hsrc + goff);
        cpasync16(dbase + MAT_B + 16,     hsrc + goff + 8);
        cpasync16(dbase + 2 * MAT_B,      lsrc + goff);
        cpasync16(dbase + 2 * MAT_B + 16, lsrc + goff + 8);
    };

    // prologue: fill ST-1 stages
    #pragma unroll
    for (int s = 0; s < ST - 1; s++) {
        issue_stage(s, s);
        asm volatile("cp.async.commit_group;" ::: "memory");
    }

    float acc[4][4][4];
    #pragma unroll
    for (int i = 0; i < 4; i++)
        #pragma unroll
        for (int j = 0; j < 4; j++)
            #pragma unroll
            for (int q = 0; q < 4; q++) acc[i][j][q] = 0.f;

    #pragma unroll 1
    for (int c = 0; c < NCH; c++) {
        // at loop top, chunks c and (maybe) c+1 are in flight
        if (c < NCH - 1) asm volatile("cp.async.wait_group 1;" ::: "memory");
        else             asm volatile("cp.async.wait_group 0;" ::: "memory");
        __syncthreads();

        if (c + 2 < NCH) {                  // buffer (c+2)%ST freed by the sync
            issue_stage((c + 2) % ST, c + 2);
            asm volatile("cp.async.commit_group;" ::: "memory");
        }

        uint32_t st = sbase + (c % ST) * STAGE_B;

        #pragma unroll
        for (int ks = 0; ks < KC / 16; ks++) {
            uint32_t kof = (uint32_t)(ks * 16 * 2);
            uint32_t afr[4][4];
            #pragma unroll
            for (int mf = 0; mf < 4; mf++)
                ldmx4(afr[mf], st + a_off + (uint32_t)(mf * 16 * SPAD * 2) + kof);
            #pragma unroll
            for (int nf = 0; nf < 4; nf++) {
                uint32_t bof = b_off + (uint32_t)(nf * 8 * SPAD * 2) + kof;
                uint32_t bh[2], bl[2];
                ldmx2(bh, st + MAT_B + bof);
                ldmx2(bl, st + 2 * MAT_B + bof);
                #pragma unroll
                for (int mf = 0; mf < 4; mf++) {
                    mma16816(acc[mf][nf], afr[mf], bh);
                    mma16816(acc[mf][nf], afr[mf], bl);
                }
            }
        }
        __syncthreads();
    }

    // epilogue: logits = acc * (1/20) + bias
    #pragma unroll
    for (int nf = 0; nf < 4; nf++) {
        int col = bn * 128 + wn * 32 + nf * 8 + 2 * tig;
        float2 bias = *(const float2*)(bp + col);
        #pragma unroll
        for (int mf = 0; mf < 4; mf++) {
            int row0 = bm * 128 + wm * 64 + mf * 16 + g;
            float2 o0, o1;
            o0.x = acc[mf][nf][0] * 0.05f + bias.x;
            o0.y = acc[mf][nf][1] * 0.05f + bias.y;
            o1.x = acc[mf][nf][2] * 0.05f + bias.x;
            o1.y = acc[mf][nf][3] * 0.05f + bias.y;
            *(float2*)(out + (size_t)row0 * VOCAB + col)       = o0;
            *(float2*)(out + (size_t)(row0 + 8) * VOCAB + col) = o1;
        }
    }
}

// ---------------- launch -----------------------------------------------------
extern "C" void kernel_launch(void* const* d_in, const int* in_sizes, int n_in,
                              void* d_out, int out_size) {
    const int*   ids  = (const int*)d_in[0];
    const float* emb  = (const float*)d_in[1];
    const float* A    = (const float*)d_in[2];
    const float* Bm   = (const float*)d_in[3];
    const float* Cm   = (const float*)d_in[4];
    const float* Dm_  = (const float*)d_in[5];
    const float* Wp   = (const float*)d_in[6];
    const float* bp   = (const float*)d_in[7];
    float*       out  = (float*)d_out;

    prep_kernel<<<256, 256>>>(A, Bm, Cm);
    split_wp_kernel<<<(VOCAB * DM + 255) / 256, 256>>>(Wp);
    zero_bits_kernel<<<256, 256>>>();
    encode_kernel<<<(ROWS * DM + 255) / 256, 256>>>(ids, emb);

    ssm_kernel<<<ROWS, 128>>>(0, 0, 1, Dm_);
    ssm_kernel<<<ROWS, 128>>>(1, 1, 0, Dm_);
    ssm_kernel<<<ROWS, 128>>>(2, 0, 1, Dm_);
    ssm_kernel<<<ROWS, 128>>>(3, 1, 0, Dm_);

    count_kernel<<<(ROWS * DM + 255) / 256, 256>>>();

    cudaFuncSetAttribute(gemm_bf16_kernel,
                         cudaFuncAttributeMaxDynamicSharedMemorySize,
                         GSMEM_BYTES);
    gemm_bf16_kernel<<<dim3(ROWS / 128, VOCAB / 128), 256, GSMEM_BYTES>>>(bp, out);
}